// round 8
// baseline (speedup 1.0000x reference)
#include <cuda_runtime.h>
#include <cuda_bf16.h>
#include <math.h>

// Problem constants
#define BB 32
#define NN 1000
#define CC 64
#define HF 12
#define WF 20
#define DD 768          // C*HF
#define NM1 999         // N-1
#define YD 72
#define OUTC 77         // 2 + 2 + 73
#define HN 75           // heads output cols (2 cls + 73 reg)

// ---------------------------------------------------------------------------
// Scratch (device globals; no runtime allocation allowed)
// ---------------------------------------------------------------------------
__device__ float g_feat[BB * NN * DD];        // (B,N,768)
__device__ float g_logits[BB * NN * NM1];     // (B,N,999)
__device__ float g_S[BB * NN * NN];           // (B,N,N) scattered softmax, zero diag
__device__ float g_att[BB * NN * DD];         // (B,N,768)
__device__ float g_ho[BB * NN * HN];          // heads GEMM result (32000 x 75)
__device__ float g_W[2 * DD * HN];            // packed [cls_w | reg_w] (1536 x 75)
__device__ int   g_mask_mode;                 // 1 = byte mask, 0 = 4-byte mask

// ---------------------------------------------------------------------------
// Mask dtype detection (bool/uint8 vs int32/float32)
// ---------------------------------------------------------------------------
__global__ __launch_bounds__(256)
void detect_mask_kernel(const unsigned int* __restrict__ w, int nwords)
{
    __shared__ int bad;
    if (threadIdx.x == 0) bad = 0;
    __syncthreads();
    int local = 0;
    for (int k = threadIdx.x; k < nwords; k += blockDim.x) {
        unsigned int v = w[k];
        if (v != 0u && v != 1u && v != 0x3F800000u) local = 1;
    }
    if (local) bad = 1;
    __syncthreads();
    if (threadIdx.x == 0) g_mask_mode = bad;   // 1 => byte mask
}

// ---------------------------------------------------------------------------
// Gather: feat[b,n,d] = invalid ? 0 : fv[b, z[n,d], y[n,d], x[n,d]]
// ---------------------------------------------------------------------------
__global__ __launch_bounds__(256)
void gather_kernel(const float* __restrict__ fv,
                   const int* __restrict__ z,
                   const int* __restrict__ y,
                   const int* __restrict__ x,
                   const void* __restrict__ mask,
                   float* __restrict__ feat,
                   int total)
{
    int idx = blockIdx.x * blockDim.x + threadIdx.x;
    if (idx >= total) return;
    int d = idx % DD;
    int rest = idx / DD;
    int n = rest % NN;
    int b = rest / NN;
    int nd = n * DD + d;

    bool inv;
    if (g_mask_mode)
        inv = ((const unsigned char*)mask)[nd] != 0;
    else
        inv = ((const unsigned int*)mask)[nd] != 0u;

    float v = 0.f;
    if (!inv) {
        int zz = z[nd], yy = y[nd], xx = x[nd];
        v = fv[((b * CC + zz) * HF + yy) * WF + xx];
    }
    feat[idx] = v;
}

// ---------------------------------------------------------------------------
// Pack heads weights: g_W[k][c] = c<2 ? cls_w[k][c] : reg_w[k][c-2]
// ---------------------------------------------------------------------------
__global__ __launch_bounds__(256)
void pack_w_kernel(const float* __restrict__ cls_w,
                   const float* __restrict__ reg_w,
                   float* __restrict__ W)
{
    int idx = blockIdx.x * blockDim.x + threadIdx.x;
    if (idx >= 2 * DD * HN) return;
    int k = idx / HN, c = idx % HN;
    W[idx] = (c < 2) ? cls_w[k * 2 + c] : reg_w[k * 73 + (c - 2)];
}

// ---------------------------------------------------------------------------
// TF32 tensor-core GEMM, 128x128 block, 4 warps, 64x64 warp tiles.
// Fragment-packed smem (single stage, 32KB static), 2 CTAs/SM co-residency
// hides LDG latency. mma.sync.m16n8k8.tf32, fp32 accumulate.
// Shared layout:
//   A frags: smA[(ks*8+mb)*128 + g*16 + tg*4 + (mlo/mhi + 2*khalf)]
//   B frags: smB[(ks*16+nb)*64 + (g*4+tg)*2 + khalf]
// MODE 0: plain A (stride lda). MODE 1: concat A=[A1|A2] rows of DD each.
// VECB: float4 B loads (ldb%4==0, full n-tiles only).
// ---------------------------------------------------------------------------
__device__ __forceinline__ float f2tf32f(float f)
{
    unsigned int r;
    asm("cvt.rna.tf32.f32 %0, %1;" : "=r"(r) : "f"(f));
    return __uint_as_float(r);
}

template<int MODE, bool ADD_BIAS, bool VECB>
__global__ __launch_bounds__(128)
void gemm_tf32_w64_kernel(const float* __restrict__ A,
                          const float* __restrict__ A2,
                          const float* __restrict__ B,
                          const float* __restrict__ bias,
                          float* __restrict__ C,
                          int M, int N, int K, int lda, int ldb,
                          size_t sA, size_t sB, size_t sC)
{
    __shared__ float smA[4096];
    __shared__ float smB[4096];

    const int tid  = threadIdx.x;
    const int lane = tid & 31;
    const int wid  = tid >> 5;          // 0..3
    const int gid  = lane >> 2;         // 0..7
    const int tg   = lane & 3;          // 0..3
    const int wm   = (wid & 1) * 64;
    const int wn   = (wid >> 1) * 64;
    const int mb0  = (wid & 1) * 4;     // 4 m16 blocks per warp
    const int nb0  = (wid >> 1) * 8;    // 8 n8 blocks per warp

    const int m0 = blockIdx.y * 128;
    const int n0 = blockIdx.x * 128;

    if (MODE == 0) A += (size_t)blockIdx.z * sA;
    B += (size_t)blockIdx.z * sB;
    C += (size_t)blockIdx.z * sC;

    float acc[4][8][4];
    #pragma unroll
    for (int i = 0; i < 4; i++)
        #pragma unroll
        for (int j = 0; j < 8; j++)
            #pragma unroll
            for (int q = 0; q < 4; q++) acc[i][j][q] = 0.f;

    for (int kt = 0; kt < K; kt += 32) {
        // --- load tiles into registers (LDG issued before the sync) ---
        float4 ra[8];
        #pragma unroll
        for (int i = 0; i < 8; i++) {
            int f4  = tid + i * 128;
            int m_l = f4 >> 3, kq = f4 & 7;
            int m = m0 + m_l, kg = kt + kq * 4;
            float4 v = make_float4(0.f, 0.f, 0.f, 0.f);
            if (m < M && kg < K) {
                const float* src;
                if (MODE == 1)
                    src = (kg < DD) ? &A[(size_t)m * DD + kg]
                                    : &A2[(size_t)m * DD + (kg - DD)];
                else
                    src = &A[(size_t)m * lda + kg];
                v = *(const float4*)src;
            }
            ra[i] = v;
        }
        float rb[8][4];
        #pragma unroll
        for (int i = 0; i < 8; i++) {
            int f4  = tid + i * 128;
            int k_l = f4 >> 5, nq = f4 & 31;
            int kg = kt + k_l, n = n0 + nq * 4;
            if (VECB) {
                float4 v = make_float4(0.f, 0.f, 0.f, 0.f);
                if (kg < K && n + 3 < N)
                    v = *(const float4*)&B[(size_t)kg * ldb + n];
                rb[i][0] = v.x; rb[i][1] = v.y; rb[i][2] = v.z; rb[i][3] = v.w;
            } else {
                #pragma unroll
                for (int c = 0; c < 4; c++) {
                    int nn = n + c;
                    rb[i][c] = (kg < K && nn < N) ? B[(size_t)kg * ldb + nn] : 0.f;
                }
            }
        }

        __syncthreads();   // previous tile's compute reads done

        // --- store to fragment-packed smem ---
        #pragma unroll
        for (int i = 0; i < 8; i++) {
            int f4  = tid + i * 128;
            int m_l = f4 >> 3, kq = f4 & 7;
            int ks = kq >> 1, half = kq & 1;
            int mb = m_l >> 4, mm = m_l & 15;
            int g = mm & 7, rh = mm >> 3;
            int r = rh + 2 * half;
            float* d = smA + (ks * 8 + mb) * 128 + g * 16 + r;
            d[0]  = f2tf32f(ra[i].x);
            d[4]  = f2tf32f(ra[i].y);
            d[8]  = f2tf32f(ra[i].z);
            d[12] = f2tf32f(ra[i].w);
        }
        #pragma unroll
        for (int i = 0; i < 8; i++) {
            int f4  = tid + i * 128;
            int k_l = f4 >> 5, nq = f4 & 31;
            int ks = k_l >> 3, kk = k_l & 7;
            int t = kk & 3, r = kk >> 2;
            #pragma unroll
            for (int c = 0; c < 4; c++) {
                int n_l = nq * 4 + c;
                int nb = n_l >> 3, g = n_l & 7;
                smB[(ks * 16 + nb) * 64 + (g * 4 + t) * 2 + r] = f2tf32f(rb[i][c]);
            }
        }

        __syncthreads();   // tile staged

        // --- compute: 4 k-slices x (4 mt x 8 nt) MMAs ---
        #pragma unroll
        for (int ks = 0; ks < 4; ks++) {
            float4 av[4];
            #pragma unroll
            for (int mt = 0; mt < 4; mt++)
                av[mt] = *(const float4*)(smA + (ks * 8 + mb0 + mt) * 128 + lane * 4);
            float2 bv[8];
            #pragma unroll
            for (int nt = 0; nt < 8; nt++)
                bv[nt] = *(const float2*)(smB + (ks * 16 + nb0 + nt) * 64 + lane * 2);
            #pragma unroll
            for (int mt = 0; mt < 4; mt++) {
                unsigned int a0 = __float_as_uint(av[mt].x);
                unsigned int a1 = __float_as_uint(av[mt].y);
                unsigned int a2 = __float_as_uint(av[mt].z);
                unsigned int a3 = __float_as_uint(av[mt].w);
                #pragma unroll
                for (int nt = 0; nt < 8; nt++) {
                    asm volatile(
                        "mma.sync.aligned.m16n8k8.row.col.f32.tf32.tf32.f32 "
                        "{%0,%1,%2,%3}, {%4,%5,%6,%7}, {%8,%9}, {%0,%1,%2,%3};\n"
                        : "+f"(acc[mt][nt][0]), "+f"(acc[mt][nt][1]),
                          "+f"(acc[mt][nt][2]), "+f"(acc[mt][nt][3])
                        : "r"(a0), "r"(a1), "r"(a2), "r"(a3),
                          "r"(__float_as_uint(bv[nt].x)),
                          "r"(__float_as_uint(bv[nt].y)));
                }
            }
        }
    }

    // --- epilogue ---
    #pragma unroll
    for (int mt = 0; mt < 4; mt++) {
        #pragma unroll
        for (int nt = 0; nt < 8; nt++) {
            int row0 = m0 + wm + mt * 16 + gid;
            int col0 = n0 + wn + nt * 8 + tg * 2;
            #pragma unroll
            for (int q = 0; q < 4; q++) {
                int row = row0 + (q >> 1) * 8;
                int col = col0 + (q & 1);
                if (row < M && col < N) {
                    float v = acc[mt][nt][q];
                    if (ADD_BIAS) v += bias[col];
                    C[(size_t)row * N + col] = v;
                }
            }
        }
    }
}

// ---------------------------------------------------------------------------
// Row softmax over 999 logits + scatter into (N x N) with zero diagonal.
// ---------------------------------------------------------------------------
__global__ __launch_bounds__(256)
void softmax_scatter_kernel(const float* __restrict__ logits,
                            float* __restrict__ S)
{
    const int i = blockIdx.x;
    const int b = blockIdx.y;
    const float* __restrict__ row = logits + ((size_t)(b * NN + i)) * NM1;
    float* __restrict__ o = S + ((size_t)(b * NN + i)) * NN;

    __shared__ float sh[8];
    const int tid = threadIdx.x;
    const int lane = tid & 31, warp = tid >> 5;

    float rv[4];
    #pragma unroll
    for (int p = 0; p < 4; p++) {
        int k = tid + 256 * p;
        rv[p] = (k < NM1) ? row[k] : -1e30f;
    }

    float m = -1e30f;
    #pragma unroll
    for (int p = 0; p < 4; p++) m = fmaxf(m, rv[p]);
    #pragma unroll
    for (int off = 16; off; off >>= 1) m = fmaxf(m, __shfl_xor_sync(0xffffffffu, m, off));
    if (lane == 0) sh[warp] = m;
    __syncthreads();
    if (warp == 0) {
        float t = (lane < 8) ? sh[lane] : -1e30f;
        #pragma unroll
        for (int off = 16; off; off >>= 1) t = fmaxf(t, __shfl_xor_sync(0xffffffffu, t, off));
        if (lane == 0) sh[0] = t;
    }
    __syncthreads();
    m = sh[0];
    __syncthreads();

    float s = 0.f;
    float ev[4];
    #pragma unroll
    for (int p = 0; p < 4; p++) {
        int k = tid + 256 * p;
        float e = (k < NM1) ? __expf(rv[p] - m) : 0.f;
        ev[p] = e;
        s += e;
    }
    #pragma unroll
    for (int off = 16; off; off >>= 1) s += __shfl_xor_sync(0xffffffffu, s, off);
    if (lane == 0) sh[warp] = s;
    __syncthreads();
    if (warp == 0) {
        float t = (lane < 8) ? sh[lane] : 0.f;
        #pragma unroll
        for (int off = 16; off; off >>= 1) t += __shfl_xor_sync(0xffffffffu, t, off);
        if (lane == 0) sh[0] = t;
    }
    __syncthreads();
    const float inv = 1.f / sh[0];

    #pragma unroll
    for (int p = 0; p < 4; p++) {
        int k = tid + 256 * p;
        if (k < NM1) {
            int j = (k < i) ? k : k + 1;
            o[j] = ev[p] * inv;
        }
    }
    if (tid == 0) o[i] = 0.f;
}

// ---------------------------------------------------------------------------
// Heads epilogue: out[r][c] from ho (32000 x 75), biases, anchors.
// ---------------------------------------------------------------------------
__global__ __launch_bounds__(256)
void heads_epilogue_kernel(const float* __restrict__ ho,
                           const float* __restrict__ cls_b,
                           const float* __restrict__ reg_b,
                           const float* __restrict__ anchors,
                           float* __restrict__ out)
{
    int idx = blockIdx.x * blockDim.x + threadIdx.x;
    if (idx >= BB * NN * OUTC) return;
    int c = idx % OUTC;
    int r = idx / OUTC;
    int n = r % NN;
    float v;
    if (c < 2)       v = ho[(size_t)r * HN + c] + cls_b[c];
    else if (c < 4)  v = anchors[n * OUTC + c];
    else             v = ho[(size_t)r * HN + (c - 2)] + reg_b[c - 4]
                         + anchors[n * OUTC + c];
    out[idx] = v;
}

// ---------------------------------------------------------------------------
// Launch
// ---------------------------------------------------------------------------
extern "C" void kernel_launch(void* const* d_in, const int* in_sizes, int n_in,
                              void* d_out, int out_size)
{
    const float* fv      = (const float*)d_in[0];
    const float* attn_w  = (const float*)d_in[1];
    const float* attn_b  = (const float*)d_in[2];
    const float* cls_w   = (const float*)d_in[3];
    const float* cls_b   = (const float*)d_in[4];
    const float* reg_w   = (const float*)d_in[5];
    const float* reg_b   = (const float*)d_in[6];
    const float* anchors = (const float*)d_in[7];
    const int*   z       = (const int*)d_in[8];
    const int*   y       = (const int*)d_in[9];
    const int*   x       = (const int*)d_in[10];
    const void*  mask    = d_in[11];
    float* out = (float*)d_out;

    float *feat, *logits, *S, *att, *ho, *W;
    cudaGetSymbolAddress((void**)&feat,   g_feat);
    cudaGetSymbolAddress((void**)&logits, g_logits);
    cudaGetSymbolAddress((void**)&S,      g_S);
    cudaGetSymbolAddress((void**)&att,    g_att);
    cudaGetSymbolAddress((void**)&ho,     g_ho);
    cudaGetSymbolAddress((void**)&W,      g_W);

    // 1) mask dtype detection
    detect_mask_kernel<<<1, 256>>>((const unsigned int*)mask, 190000);

    // 2) gather
    {
        int total = BB * NN * DD;
        gather_kernel<<<(total + 255) / 256, 256>>>(fv, z, y, x, mask, feat, total);
    }

    // 2b) pack heads weights
    pack_w_kernel<<<(2 * DD * HN + 255) / 256, 256>>>(cls_w, reg_w, W);

    // 3) logits = feat @ attn_w + attn_b   (per batch 1000x999, K=768; ldb=999 -> scalar B)
    {
        dim3 grid((NM1 + 127) / 128, (NN + 127) / 128, BB);
        gemm_tf32_w64_kernel<0, true, false><<<grid, 128>>>(
            feat, nullptr, attn_w, attn_b, logits,
            NN, NM1, DD, DD, NM1,
            (size_t)NN * DD, 0, (size_t)NN * NM1);
    }

    // 4) softmax + scatter
    {
        dim3 grid(NN, BB);
        softmax_scatter_kernel<<<grid, 256>>>(logits, S);
    }

    // 5) att = S @ feat                    (per batch 1000x768, K=1000; ldb=768 -> vec B)
    {
        dim3 grid((DD + 127) / 128, (NN + 127) / 128, BB);
        gemm_tf32_w64_kernel<0, false, true><<<grid, 128>>>(
            S, nullptr, feat, nullptr, att,
            NN, DD, NN, NN, DD,
            (size_t)NN * NN, (size_t)NN * DD, (size_t)NN * DD);
    }

    // 6) heads GEMM: [att|feat] (32000 x 1536) @ W (1536 x 75; ldb=75 -> scalar B)
    {
        dim3 grid(1, (BB * NN + 127) / 128, 1);
        gemm_tf32_w64_kernel<1, false, false><<<grid, 128>>>(
            att, feat, W, nullptr, ho,
            BB * NN, HN, 2 * DD, 0, HN,
            0, 0, 0);
    }

    // 7) heads epilogue
    {
        int total = BB * NN * OUTC;
        heads_epilogue_kernel<<<(total + 255) / 256, 256>>>(ho, cls_b, reg_b,
                                                            anchors, out);
    }
}

// round 10
// speedup vs baseline: 2.2756x; 2.2756x over previous
#include <cuda_runtime.h>
#include <cuda_bf16.h>
#include <math.h>

// Problem constants
#define BB 32
#define NN 1000
#define CC 64
#define HF 12
#define WF 20
#define DD 768          // C*HF
#define NM1 999         // N-1
#define YD 72
#define OUTC 77         // 2 + 2 + 73
#define HN 75           // heads output cols (2 cls + 73 reg)

// GEMM smem layout (floats)
#define SA_STRIDE 36            // 32 k + 4 pad
#define SB_STRIDE 136           // 128 n + 8 pad
#define SA_STAGE  (128 * SA_STRIDE)   // 4608
#define SB_STAGE  (32 * SB_STRIDE)    // 4352
#define SB_BASE   (2 * SA_STAGE)      // 9216
#define GEMM_SMEM ((2 * SA_STAGE + 2 * SB_STAGE) * 4)   // 71680 bytes

// ---------------------------------------------------------------------------
// Scratch (device globals; no runtime allocation allowed)
// ---------------------------------------------------------------------------
__device__ float g_feat[BB * NN * DD];        // (B,N,768)
__device__ float g_logits[BB * NN * NM1];     // (B,N,999)
__device__ float g_S[BB * NN * NN];           // (B,N,N) scattered softmax, zero diag
__device__ float g_att[BB * NN * DD];         // (B,N,768)
__device__ float g_ho[BB * NN * HN];          // heads GEMM result (32000 x 75)
__device__ float g_W[2 * DD * HN];            // packed [cls_w | reg_w] (1536 x 75)
__device__ int   g_mask_mode;                 // 1 = byte mask, 0 = 4-byte mask

// ---------------------------------------------------------------------------
// PTX helpers
// ---------------------------------------------------------------------------
__device__ __forceinline__ unsigned int smem_u32(const void* p)
{
    unsigned int a;
    asm("{ .reg .u64 t; cvta.to.shared.u64 t, %1; cvt.u32.u64 %0, t; }"
        : "=r"(a) : "l"(p));
    return a;
}

__device__ __forceinline__ void cp_async16(unsigned int dst, const void* src, int sz)
{
    asm volatile("cp.async.ca.shared.global [%0], [%1], 16, %2;"
                 :: "r"(dst), "l"(src), "r"(sz));
}

__device__ __forceinline__ void cp_async4(unsigned int dst, const void* src, int sz)
{
    asm volatile("cp.async.ca.shared.global [%0], [%1], 4, %2;"
                 :: "r"(dst), "l"(src), "r"(sz));
}

__device__ __forceinline__ void cp_commit()
{
    asm volatile("cp.async.commit_group;");
}

template<int N>
__device__ __forceinline__ void cp_wait()
{
    asm volatile("cp.async.wait_group %0;" :: "n"(N));
}

__device__ __forceinline__ unsigned int f2tf32(float f)
{
    unsigned int r;
    asm("cvt.rna.tf32.f32 %0, %1;" : "=r"(r) : "f"(f));
    return r;
}

// ---------------------------------------------------------------------------
// Mask dtype detection (bool/uint8 vs int32/float32)
// ---------------------------------------------------------------------------
__global__ __launch_bounds__(256)
void detect_mask_kernel(const unsigned int* __restrict__ w, int nwords)
{
    __shared__ int bad;
    if (threadIdx.x == 0) bad = 0;
    __syncthreads();
    int local = 0;
    for (int k = threadIdx.x; k < nwords; k += blockDim.x) {
        unsigned int v = w[k];
        if (v != 0u && v != 1u && v != 0x3F800000u) local = 1;
    }
    if (local) bad = 1;
    __syncthreads();
    if (threadIdx.x == 0) g_mask_mode = bad;   // 1 => byte mask
}

// ---------------------------------------------------------------------------
// Gather: feat[b,n,d] = invalid ? 0 : fv[b, z[n,d], y[n,d], x[n,d]]
// ---------------------------------------------------------------------------
__global__ __launch_bounds__(256)
void gather_kernel(const float* __restrict__ fv,
                   const int* __restrict__ z,
                   const int* __restrict__ y,
                   const int* __restrict__ x,
                   const void* __restrict__ mask,
                   float* __restrict__ feat,
                   int total)
{
    int idx = blockIdx.x * blockDim.x + threadIdx.x;
    if (idx >= total) return;
    int d = idx % DD;
    int rest = idx / DD;
    int n = rest % NN;
    int b = rest / NN;
    int nd = n * DD + d;

    bool inv;
    if (g_mask_mode)
        inv = ((const unsigned char*)mask)[nd] != 0;
    else
        inv = ((const unsigned int*)mask)[nd] != 0u;

    float v = 0.f;
    if (!inv) {
        int zz = z[nd], yy = y[nd], xx = x[nd];
        v = fv[((b * CC + zz) * HF + yy) * WF + xx];
    }
    feat[idx] = v;
}

// ---------------------------------------------------------------------------
// Pack heads weights: g_W[k][c] = c<2 ? cls_w[k][c] : reg_w[k][c-2]
// ---------------------------------------------------------------------------
__global__ __launch_bounds__(256)
void pack_w_kernel(const float* __restrict__ cls_w,
                   const float* __restrict__ reg_w,
                   float* __restrict__ W)
{
    int idx = blockIdx.x * blockDim.x + threadIdx.x;
    if (idx >= 2 * DD * HN) return;
    int k = idx / HN, c = idx % HN;
    W[idx] = (c < 2) ? cls_w[k * 2 + c] : reg_w[k * 73 + (c - 2)];
}

// ---------------------------------------------------------------------------
// TF32 tensor-core GEMM, 128x128 block, Ktile 32, 256 threads, 8 warps,
// warp tile 32x64.  cp.async staging into padded natural layouts:
//   As[m][k] stride 36  (conflict-free scalar fragment loads)
//   Bs[k][n] stride 136 (conflict-free scalar fragment loads)
// 2-stage pipeline via cp.async commit/wait.  tf32 cvt post-LDS (rna).
// MODE 0: plain A (stride lda). MODE 1: concat A=[A1|A2] rows of DD each.
// VECB: 16B B copies (requires ldb%4==0 and N multiple of 128).
// ---------------------------------------------------------------------------
template<int MODE, bool ADD_BIAS, bool VECB>
__global__ __launch_bounds__(256)
void gemm_tf32_cp_kernel(const float* __restrict__ A,
                         const float* __restrict__ A2,
                         const float* __restrict__ B,
                         const float* __restrict__ bias,
                         float* __restrict__ C,
                         int M, int N, int K, int lda, int ldb,
                         size_t sA, size_t sB, size_t sC)
{
    extern __shared__ float sm[];

    const int tid  = threadIdx.x;
    const int lane = tid & 31;
    const int wid  = tid >> 5;
    const int gid  = lane >> 2;     // 0..7
    const int tg   = lane & 3;      // 0..3
    const int wm   = (wid & 3) * 32;
    const int wn   = (wid >> 2) * 64;

    const int m0 = blockIdx.y * 128;
    const int n0 = blockIdx.x * 128;

    if (MODE == 0) A += (size_t)blockIdx.z * sA;
    B += (size_t)blockIdx.z * sB;
    C += (size_t)blockIdx.z * sC;

    const unsigned int smA_u = smem_u32(sm);
    const unsigned int smB_u = smem_u32(sm + SB_BASE);

    float acc[2][8][4];
    #pragma unroll
    for (int i = 0; i < 2; i++)
        #pragma unroll
        for (int j = 0; j < 8; j++)
            #pragma unroll
            for (int q = 0; q < 4; q++) acc[i][j][q] = 0.f;

    // ---- stage issue: cp.async all of A-tile and B-tile for kt into stage st
    auto stage = [&](int kt, int st) {
        // A: 128 rows x 32 k = 1024 16B-chunks; 4 per thread
        unsigned int abase = smA_u + st * (SA_STAGE * 4);
        #pragma unroll
        for (int i = 0; i < 4; i++) {
            int c   = tid + i * 256;
            int m_l = c >> 3, kq = c & 7;
            int m = m0 + m_l, kg = kt + kq * 4;
            const float* src;
            int sz = 0;
            if (m < M && kg < K) {
                if (MODE == 1)
                    src = (kg < DD) ? &A[(size_t)m * DD + kg]
                                    : &A2[(size_t)m * DD + (kg - DD)];
                else
                    src = &A[(size_t)m * lda + kg];
                int rem = (K - kg) * 4;
                sz = rem < 16 ? rem : 16;
            } else {
                src = A;
            }
            cp_async16(abase + (m_l * SA_STRIDE + kq * 4) * 4, src, sz);
        }
        // B
        unsigned int bbase = smB_u + st * (SB_STAGE * 4);
        if (VECB) {
            // 32 k x 128 n = 1024 16B-chunks; 4 per thread
            #pragma unroll
            for (int i = 0; i < 4; i++) {
                int c   = tid + i * 256;
                int k_l = c >> 5, nq = c & 31;
                int kg = kt + k_l;
                const float* src = (kg < K) ? &B[(size_t)kg * ldb + n0 + nq * 4] : B;
                int sz = (kg < K) ? 16 : 0;
                cp_async16(bbase + (k_l * SB_STRIDE + nq * 4) * 4, src, sz);
            }
        } else {
            // 32 k x 128 n scalars; 16 per thread
            #pragma unroll
            for (int i = 0; i < 16; i++) {
                int c   = tid + i * 256;
                int k_l = c >> 7, n_l = c & 127;
                int kg = kt + k_l, n = n0 + n_l;
                bool ok = (kg < K) && (n < N);
                const float* src = ok ? &B[(size_t)kg * ldb + n] : B;
                cp_async4(bbase + (k_l * SB_STRIDE + n_l) * 4, src, ok ? 4 : 0);
            }
        }
    };

    auto compute = [&](int st) {
        const float* Ab = sm + st * SA_STAGE;
        const float* Bb = sm + SB_BASE + st * SB_STAGE;
        #pragma unroll
        for (int ks = 0; ks < 4; ks++) {
            const int k0 = ks * 8;
            unsigned int a[2][4], bf[8][2];
            #pragma unroll
            for (int mt = 0; mt < 2; mt++) {
                int ar = wm + mt * 16 + gid;
                a[mt][0] = f2tf32(Ab[ar       * SA_STRIDE + k0 + tg]);
                a[mt][1] = f2tf32(Ab[(ar + 8) * SA_STRIDE + k0 + tg]);
                a[mt][2] = f2tf32(Ab[ar       * SA_STRIDE + k0 + tg + 4]);
                a[mt][3] = f2tf32(Ab[(ar + 8) * SA_STRIDE + k0 + tg + 4]);
            }
            #pragma unroll
            for (int nt = 0; nt < 8; nt++) {
                int bc = wn + nt * 8 + gid;
                bf[nt][0] = f2tf32(Bb[(k0 + tg)     * SB_STRIDE + bc]);
                bf[nt][1] = f2tf32(Bb[(k0 + tg + 4) * SB_STRIDE + bc]);
            }
            #pragma unroll
            for (int mt = 0; mt < 2; mt++)
                #pragma unroll
                for (int nt = 0; nt < 8; nt++) {
                    asm volatile(
                        "mma.sync.aligned.m16n8k8.row.col.f32.tf32.tf32.f32 "
                        "{%0,%1,%2,%3}, {%4,%5,%6,%7}, {%8,%9}, {%0,%1,%2,%3};\n"
                        : "+f"(acc[mt][nt][0]), "+f"(acc[mt][nt][1]),
                          "+f"(acc[mt][nt][2]), "+f"(acc[mt][nt][3])
                        : "r"(a[mt][0]), "r"(a[mt][1]), "r"(a[mt][2]), "r"(a[mt][3]),
                          "r"(bf[nt][0]), "r"(bf[nt][1]));
                }
        }
    };

    // ---- 2-stage pipeline ----
    stage(0, 0);
    cp_commit();

    int st = 0;
    for (int kt = 0; kt < K; kt += 32) {
        bool has_next = (kt + 32) < K;
        if (has_next) {
            stage(kt + 32, st ^ 1);
            cp_commit();
            cp_wait<1>();
        } else {
            cp_wait<0>();
        }
        __syncthreads();          // stage st fully visible
        compute(st);
        __syncthreads();          // done reading st before it is overwritten
        st ^= 1;
    }

    // ---- epilogue ----
    #pragma unroll
    for (int mt = 0; mt < 2; mt++) {
        #pragma unroll
        for (int nt = 0; nt < 8; nt++) {
            int row0 = m0 + wm + mt * 16 + gid;
            int col0 = n0 + wn + nt * 8 + tg * 2;
            #pragma unroll
            for (int q = 0; q < 4; q++) {
                int row = row0 + (q >> 1) * 8;
                int col = col0 + (q & 1);
                if (row < M && col < N) {
                    float v = acc[mt][nt][q];
                    if (ADD_BIAS) v += bias[col];
                    C[(size_t)row * N + col] = v;
                }
            }
        }
    }
}

// ---------------------------------------------------------------------------
// Row softmax over 999 logits + scatter into (N x N) with zero diagonal.
// ---------------------------------------------------------------------------
__global__ __launch_bounds__(256)
void softmax_scatter_kernel(const float* __restrict__ logits,
                            float* __restrict__ S)
{
    const int i = blockIdx.x;
    const int b = blockIdx.y;
    const float* __restrict__ row = logits + ((size_t)(b * NN + i)) * NM1;
    float* __restrict__ o = S + ((size_t)(b * NN + i)) * NN;

    __shared__ float sh[8];
    const int tid = threadIdx.x;
    const int lane = tid & 31, warp = tid >> 5;

    float rv[4];
    #pragma unroll
    for (int p = 0; p < 4; p++) {
        int k = tid + 256 * p;
        rv[p] = (k < NM1) ? row[k] : -1e30f;
    }

    float m = -1e30f;
    #pragma unroll
    for (int p = 0; p < 4; p++) m = fmaxf(m, rv[p]);
    #pragma unroll
    for (int off = 16; off; off >>= 1) m = fmaxf(m, __shfl_xor_sync(0xffffffffu, m, off));
    if (lane == 0) sh[warp] = m;
    __syncthreads();
    if (warp == 0) {
        float t = (lane < 8) ? sh[lane] : -1e30f;
        #pragma unroll
        for (int off = 16; off; off >>= 1) t = fmaxf(t, __shfl_xor_sync(0xffffffffu, t, off));
        if (lane == 0) sh[0] = t;
    }
    __syncthreads();
    m = sh[0];
    __syncthreads();

    float s = 0.f;
    float ev[4];
    #pragma unroll
    for (int p = 0; p < 4; p++) {
        int k = tid + 256 * p;
        float e = (k < NM1) ? __expf(rv[p] - m) : 0.f;
        ev[p] = e;
        s += e;
    }
    #pragma unroll
    for (int off = 16; off; off >>= 1) s += __shfl_xor_sync(0xffffffffu, s, off);
    if (lane == 0) sh[warp] = s;
    __syncthreads();
    if (warp == 0) {
        float t = (lane < 8) ? sh[lane] : 0.f;
        #pragma unroll
        for (int off = 16; off; off >>= 1) t += __shfl_xor_sync(0xffffffffu, t, off);
        if (lane == 0) sh[0] = t;
    }
    __syncthreads();
    const float inv = 1.f / sh[0];

    #pragma unroll
    for (int p = 0; p < 4; p++) {
        int k = tid + 256 * p;
        if (k < NM1) {
            int j = (k < i) ? k : k + 1;
            o[j] = ev[p] * inv;
        }
    }
    if (tid == 0) o[i] = 0.f;
}

// ---------------------------------------------------------------------------
// Heads epilogue: out[r][c] from ho (32000 x 75), biases, anchors.
// ---------------------------------------------------------------------------
__global__ __launch_bounds__(256)
void heads_epilogue_kernel(const float* __restrict__ ho,
                           const float* __restrict__ cls_b,
                           const float* __restrict__ reg_b,
                           const float* __restrict__ anchors,
                           float* __restrict__ out)
{
    int idx = blockIdx.x * blockDim.x + threadIdx.x;
    if (idx >= BB * NN * OUTC) return;
    int c = idx % OUTC;
    int r = idx / OUTC;
    int n = r % NN;
    float v;
    if (c < 2)       v = ho[(size_t)r * HN + c] + cls_b[c];
    else if (c < 4)  v = anchors[n * OUTC + c];
    else             v = ho[(size_t)r * HN + (c - 2)] + reg_b[c - 4]
                         + anchors[n * OUTC + c];
    out[idx] = v;
}

// ---------------------------------------------------------------------------
// Launch
// ---------------------------------------------------------------------------
extern "C" void kernel_launch(void* const* d_in, const int* in_sizes, int n_in,
                              void* d_out, int out_size)
{
    const float* fv      = (const float*)d_in[0];
    const float* attn_w  = (const float*)d_in[1];
    const float* attn_b  = (const float*)d_in[2];
    const float* cls_w   = (const float*)d_in[3];
    const float* cls_b   = (const float*)d_in[4];
    const float* reg_w   = (const float*)d_in[5];
    const float* reg_b   = (const float*)d_in[6];
    const float* anchors = (const float*)d_in[7];
    const int*   z       = (const int*)d_in[8];
    const int*   y       = (const int*)d_in[9];
    const int*   x       = (const int*)d_in[10];
    const void*  mask    = d_in[11];
    float* out = (float*)d_out;

    float *feat, *logits, *S, *att, *ho, *W;
    cudaGetSymbolAddress((void**)&feat,   g_feat);
    cudaGetSymbolAddress((void**)&logits, g_logits);
    cudaGetSymbolAddress((void**)&S,      g_S);
    cudaGetSymbolAddress((void**)&att,    g_att);
    cudaGetSymbolAddress((void**)&ho,     g_ho);
    cudaGetSymbolAddress((void**)&W,      g_W);

    static int attr_done = 0;
    if (!attr_done) {
        cudaFuncSetAttribute(gemm_tf32_cp_kernel<0, true,  false>,
                             cudaFuncAttributeMaxDynamicSharedMemorySize, GEMM_SMEM);
        cudaFuncSetAttribute(gemm_tf32_cp_kernel<0, false, true>,
                             cudaFuncAttributeMaxDynamicSharedMemorySize, GEMM_SMEM);
        cudaFuncSetAttribute(gemm_tf32_cp_kernel<1, false, false>,
                             cudaFuncAttributeMaxDynamicSharedMemorySize, GEMM_SMEM);
        attr_done = 1;
    }

    // 1) mask dtype detection
    detect_mask_kernel<<<1, 256>>>((const unsigned int*)mask, 190000);

    // 2) gather
    {
        int total = BB * NN * DD;
        gather_kernel<<<(total + 255) / 256, 256>>>(fv, z, y, x, mask, feat, total);
    }

    // 2b) pack heads weights
    pack_w_kernel<<<(2 * DD * HN + 255) / 256, 256>>>(cls_w, reg_w, W);

    // 3) logits = feat @ attn_w + attn_b   (per batch 1000x999, K=768; ldb=999 -> 4B cp.async)
    {
        dim3 grid((NM1 + 127) / 128, (NN + 127) / 128, BB);
        gemm_tf32_cp_kernel<0, true, false><<<grid, 256, GEMM_SMEM>>>(
            feat, nullptr, attn_w, attn_b, logits,
            NN, NM1, DD, DD, NM1,
            (size_t)NN * DD, 0, (size_t)NN * NM1);
    }

    // 4) softmax + scatter
    {
        dim3 grid(NN, BB);
        softmax_scatter_kernel<<<grid, 256>>>(logits, S);
    }

    // 5) att = S @ feat                    (per batch 1000x768, K=1000; ldb=768 -> 16B cp.async)
    {
        dim3 grid((DD + 127) / 128, (NN + 127) / 128, BB);
        gemm_tf32_cp_kernel<0, false, true><<<grid, 256, GEMM_SMEM>>>(
            S, nullptr, feat, nullptr, att,
            NN, DD, NN, NN, DD,
            (size_t)NN * NN, (size_t)NN * DD, (size_t)NN * DD);
    }

    // 6) heads GEMM: [att|feat] (32000 x 1536) @ W (1536 x 75; ldb=75 -> 4B cp.async)
    {
        dim3 grid(1, (BB * NN + 127) / 128, 1);
        gemm_tf32_cp_kernel<1, false, false><<<grid, 256, GEMM_SMEM>>>(
            att, feat, W, nullptr, ho,
            BB * NN, HN, 2 * DD, 0, HN,
            0, 0, 0);
    }

    // 7) heads epilogue
    {
        int total = BB * NN * OUTC;
        heads_epilogue_kernel<<<(total + 255) / 256, 256>>>(ho, cls_b, reg_b,
                                                            anchors, out);
    }
}

// round 11
// speedup vs baseline: 2.5216x; 1.1081x over previous
#include <cuda_runtime.h>
#include <cuda_bf16.h>
#include <math.h>

// Problem constants
#define BB 32
#define NN 1000
#define CC 64
#define HF 12
#define WF 20
#define DD 768          // C*HF
#define NM1 999         // N-1
#define YD 72
#define OUTC 77         // 2 + 2 + 73
#define HN 75           // heads output cols (2 cls + 73 reg)
#define BTPAD 1000      // padded attn_w row stride

// GEMM smem layout (floats)
#define SA_STRIDE 36            // 32 k + 4 pad
#define SB_STRIDE 136           // 128 n + 8 pad
#define SA_STAGE  (128 * SA_STRIDE)   // 4608
#define SB_STAGE  (32 * SB_STRIDE)    // 4352
#define SB_BASE   (2 * SA_STAGE)      // 9216
#define GEMM_SMEM ((2 * SA_STAGE + 2 * SB_STAGE) * 4)   // 71680 bytes

// ---------------------------------------------------------------------------
// Scratch (device globals; no runtime allocation allowed)
// ---------------------------------------------------------------------------
__device__ float g_feat[BB * NN * DD];        // (B,N,768) tf32-rounded
__device__ float g_logits[BB * NN * NM1];     // (B,N,999) fp32
__device__ float g_S[BB * NN * NN];           // (B,N,N) tf32-rounded softmax
__device__ float g_att[BB * NN * DD];         // (B,N,768) tf32-rounded
__device__ float g_ho[BB * NN * HN];          // heads GEMM result (32000 x 75)
__device__ float g_W[2 * DD * HN];            // packed [cls_w|reg_w], tf32-rounded
__device__ float g_Bt[DD * BTPAD];            // attn_w padded to stride 1000, rounded
__device__ int   g_mask_mode;                 // 1 = byte mask, 0 = 4-byte mask

// ---------------------------------------------------------------------------
// PTX helpers
// ---------------------------------------------------------------------------
__device__ __forceinline__ unsigned int smem_u32(const void* p)
{
    unsigned int a;
    asm("{ .reg .u64 t; cvta.to.shared.u64 t, %1; cvt.u32.u64 %0, t; }"
        : "=r"(a) : "l"(p));
    return a;
}

__device__ __forceinline__ void cp_async16(unsigned int dst, const void* src, int sz)
{
    asm volatile("cp.async.ca.shared.global [%0], [%1], 16, %2;"
                 :: "r"(dst), "l"(src), "r"(sz));
}

__device__ __forceinline__ void cp_async4(unsigned int dst, const void* src, int sz)
{
    asm volatile("cp.async.ca.shared.global [%0], [%1], 4, %2;"
                 :: "r"(dst), "l"(src), "r"(sz));
}

__device__ __forceinline__ void cp_commit()
{
    asm volatile("cp.async.commit_group;");
}

template<int N>
__device__ __forceinline__ void cp_wait()
{
    asm volatile("cp.async.wait_group %0;" :: "n"(N));
}

__device__ __forceinline__ float f2tf32f(float f)
{
    unsigned int r;
    asm("cvt.rna.tf32.f32 %0, %1;" : "=r"(r) : "f"(f));
    return __uint_as_float(r);
}

// ---------------------------------------------------------------------------
// Mask dtype detection (bool/uint8 vs int32/float32)
// ---------------------------------------------------------------------------
__global__ __launch_bounds__(256)
void detect_mask_kernel(const unsigned int* __restrict__ w, int nwords)
{
    __shared__ int bad;
    if (threadIdx.x == 0) bad = 0;
    __syncthreads();
    int local = 0;
    for (int k = threadIdx.x; k < nwords; k += blockDim.x) {
        unsigned int v = w[k];
        if (v != 0u && v != 1u && v != 0x3F800000u) local = 1;
    }
    if (local) bad = 1;
    __syncthreads();
    if (threadIdx.x == 0) g_mask_mode = bad;   // 1 => byte mask
}

// ---------------------------------------------------------------------------
// Gather (writes tf32-rounded feat)
// ---------------------------------------------------------------------------
__global__ __launch_bounds__(256)
void gather_kernel(const float* __restrict__ fv,
                   const int* __restrict__ z,
                   const int* __restrict__ y,
                   const int* __restrict__ x,
                   const void* __restrict__ mask,
                   float* __restrict__ feat,
                   int total)
{
    int idx = blockIdx.x * blockDim.x + threadIdx.x;
    if (idx >= total) return;
    int d = idx % DD;
    int rest = idx / DD;
    int n = rest % NN;
    int b = rest / NN;
    int nd = n * DD + d;

    bool inv;
    if (g_mask_mode)
        inv = ((const unsigned char*)mask)[nd] != 0;
    else
        inv = ((const unsigned int*)mask)[nd] != 0u;

    float v = 0.f;
    if (!inv) {
        int zz = z[nd], yy = y[nd], xx = x[nd];
        v = fv[((b * CC + zz) * HF + yy) * WF + xx];
    }
    feat[idx] = f2tf32f(v);
}

// ---------------------------------------------------------------------------
// Prep attn_w: pad 999 -> 1000 row stride + tf32 round.
// ---------------------------------------------------------------------------
__global__ __launch_bounds__(256)
void prep_attnw_kernel(const float* __restrict__ w, float* __restrict__ out)
{
    int idx = blockIdx.x * blockDim.x + threadIdx.x;
    if (idx >= DD * BTPAD) return;
    int k = idx / BTPAD, n = idx % BTPAD;
    out[idx] = (n < NM1) ? f2tf32f(w[k * NM1 + n]) : 0.f;
}

// ---------------------------------------------------------------------------
// Pack heads weights (tf32-rounded)
// ---------------------------------------------------------------------------
__global__ __launch_bounds__(256)
void pack_w_kernel(const float* __restrict__ cls_w,
                   const float* __restrict__ reg_w,
                   float* __restrict__ W)
{
    int idx = blockIdx.x * blockDim.x + threadIdx.x;
    if (idx >= 2 * DD * HN) return;
    int k = idx / HN, c = idx % HN;
    float v = (c < 2) ? cls_w[k * 2 + c] : reg_w[k * 73 + (c - 2)];
    W[idx] = f2tf32f(v);
}

// ---------------------------------------------------------------------------
// TF32 tensor-core GEMM, 128x128 block, Ktile 32, 256 threads, 8 warps,
// warp tile 32x64.  Operands pre-rounded to tf32; mainloop is LDS+HMMA only.
//   As[m][k] stride 36  (conflict-free fragment loads)
//   Bs[k][n] stride 136 (conflict-free fragment loads)
// 2-stage cp.async pipeline.
// MODE 0: plain A (stride lda). MODE 1: concat A=[A1|A2] rows of DD each.
// VECB: 16B B copies (ldb%4==0, buffer padded so n0+127 in-bounds or sz-guarded).
// ROUND_OUT: tf32-round C before store (for GEMM2 -> heads A).
// ---------------------------------------------------------------------------
template<int MODE, bool ADD_BIAS, bool VECB, bool ROUND_OUT>
__global__ __launch_bounds__(256)
void gemm_tf32_cp_kernel(const float* __restrict__ A,
                         const float* __restrict__ A2,
                         const float* __restrict__ B,
                         const float* __restrict__ bias,
                         float* __restrict__ C,
                         int M, int N, int K, int lda, int ldb,
                         size_t sA, size_t sB, size_t sC)
{
    extern __shared__ float sm[];

    const int tid  = threadIdx.x;
    const int lane = tid & 31;
    const int wid  = tid >> 5;
    const int gid  = lane >> 2;     // 0..7
    const int tg   = lane & 3;      // 0..3
    const int wm   = (wid & 3) * 32;
    const int wn   = (wid >> 2) * 64;

    const int m0 = blockIdx.y * 128;
    const int n0 = blockIdx.x * 128;

    if (MODE == 0) A += (size_t)blockIdx.z * sA;
    B += (size_t)blockIdx.z * sB;
    C += (size_t)blockIdx.z * sC;

    const unsigned int smA_u = smem_u32(sm);
    const unsigned int smB_u = smem_u32(sm + SB_BASE);

    float acc[2][8][4];
    #pragma unroll
    for (int i = 0; i < 2; i++)
        #pragma unroll
        for (int j = 0; j < 8; j++)
            #pragma unroll
            for (int q = 0; q < 4; q++) acc[i][j][q] = 0.f;

    // ---- stage: cp.async A-tile and B-tile for kt into stage st
    auto stage = [&](int kt, int st) {
        unsigned int abase = smA_u + st * (SA_STAGE * 4);
        #pragma unroll
        for (int i = 0; i < 4; i++) {
            int c   = tid + i * 256;
            int m_l = c >> 3, kq = c & 7;
            int m = m0 + m_l, kg = kt + kq * 4;
            const float* src;
            int sz = 0;
            if (m < M && kg < K) {
                if (MODE == 1)
                    src = (kg < DD) ? &A[(size_t)m * DD + kg]
                                    : &A2[(size_t)m * DD + (kg - DD)];
                else
                    src = &A[(size_t)m * lda + kg];
                int rem = (K - kg) * 4;
                sz = rem < 16 ? rem : 16;
            } else {
                src = A;
            }
            cp_async16(abase + (m_l * SA_STRIDE + kq * 4) * 4, src, sz);
        }
        unsigned int bbase = smB_u + st * (SB_STAGE * 4);
        if (VECB) {
            #pragma unroll
            for (int i = 0; i < 4; i++) {
                int c   = tid + i * 256;
                int k_l = c >> 5, nq = c & 31;
                int kg = kt + k_l;
                int n  = n0 + nq * 4;
                bool ok = (kg < K) && (n + 3 < ((N + 3) & ~3) + 1);  // buffer padded
                const float* src = (kg < K) ? &B[(size_t)kg * ldb + n] : B;
                int sz = (kg < K) ? 16 : 0;
                (void)ok;
                cp_async16(bbase + (k_l * SB_STRIDE + nq * 4) * 4, src, sz);
            }
        } else {
            #pragma unroll
            for (int i = 0; i < 16; i++) {
                int c   = tid + i * 256;
                int k_l = c >> 7, n_l = c & 127;
                int kg = kt + k_l, n = n0 + n_l;
                bool ok = (kg < K) && (n < N);
                const float* src = ok ? &B[(size_t)kg * ldb + n] : B;
                cp_async4(bbase + (k_l * SB_STRIDE + n_l) * 4, src, ok ? 4 : 0);
            }
        }
    };

    auto compute = [&](int st) {
        const unsigned int* Ab = (const unsigned int*)(sm + st * SA_STAGE);
        const unsigned int* Bb = (const unsigned int*)(sm + SB_BASE + st * SB_STAGE);
        #pragma unroll
        for (int ks = 0; ks < 4; ks++) {
            const int k0 = ks * 8;
            unsigned int a[2][4], bf[8][2];
            #pragma unroll
            for (int mt = 0; mt < 2; mt++) {
                int ar = wm + mt * 16 + gid;
                a[mt][0] = Ab[ar       * SA_STRIDE + k0 + tg];
                a[mt][1] = Ab[(ar + 8) * SA_STRIDE + k0 + tg];
                a[mt][2] = Ab[ar       * SA_STRIDE + k0 + tg + 4];
                a[mt][3] = Ab[(ar + 8) * SA_STRIDE + k0 + tg + 4];
            }
            #pragma unroll
            for (int nt = 0; nt < 8; nt++) {
                int bc = wn + nt * 8 + gid;
                bf[nt][0] = Bb[(k0 + tg)     * SB_STRIDE + bc];
                bf[nt][1] = Bb[(k0 + tg + 4) * SB_STRIDE + bc];
            }
            #pragma unroll
            for (int mt = 0; mt < 2; mt++)
                #pragma unroll
                for (int nt = 0; nt < 8; nt++) {
                    asm volatile(
                        "mma.sync.aligned.m16n8k8.row.col.f32.tf32.tf32.f32 "
                        "{%0,%1,%2,%3}, {%4,%5,%6,%7}, {%8,%9}, {%0,%1,%2,%3};\n"
                        : "+f"(acc[mt][nt][0]), "+f"(acc[mt][nt][1]),
                          "+f"(acc[mt][nt][2]), "+f"(acc[mt][nt][3])
                        : "r"(a[mt][0]), "r"(a[mt][1]), "r"(a[mt][2]), "r"(a[mt][3]),
                          "r"(bf[nt][0]), "r"(bf[nt][1]));
                }
        }
    };

    // ---- 2-stage pipeline ----
    stage(0, 0);
    cp_commit();

    int st = 0;
    for (int kt = 0; kt < K; kt += 32) {
        bool has_next = (kt + 32) < K;
        if (has_next) {
            stage(kt + 32, st ^ 1);
            cp_commit();
            cp_wait<1>();
        } else {
            cp_wait<0>();
        }
        __syncthreads();
        compute(st);
        __syncthreads();
        st ^= 1;
    }

    // ---- epilogue ----
    #pragma unroll
    for (int mt = 0; mt < 2; mt++) {
        #pragma unroll
        for (int nt = 0; nt < 8; nt++) {
            int row0 = m0 + wm + mt * 16 + gid;
            int col0 = n0 + wn + nt * 8 + tg * 2;
            #pragma unroll
            for (int q = 0; q < 4; q++) {
                int row = row0 + (q >> 1) * 8;
                int col = col0 + (q & 1);
                if (row < M && col < N) {
                    float v = acc[mt][nt][q];
                    if (ADD_BIAS) v += bias[col];
                    if (ROUND_OUT) v = f2tf32f(v);
                    C[(size_t)row * N + col] = v;
                }
            }
        }
    }
}

// ---------------------------------------------------------------------------
// Row softmax over 999 logits + scatter into (N x N) with zero diagonal.
// Output tf32-rounded (consumed only by GEMM2 A).
// ---------------------------------------------------------------------------
__global__ __launch_bounds__(256)
void softmax_scatter_kernel(const float* __restrict__ logits,
                            float* __restrict__ S)
{
    const int i = blockIdx.x;
    const int b = blockIdx.y;
    const float* __restrict__ row = logits + ((size_t)(b * NN + i)) * NM1;
    float* __restrict__ o = S + ((size_t)(b * NN + i)) * NN;

    __shared__ float sh[8];
    const int tid = threadIdx.x;
    const int lane = tid & 31, warp = tid >> 5;

    float rv[4];
    #pragma unroll
    for (int p = 0; p < 4; p++) {
        int k = tid + 256 * p;
        rv[p] = (k < NM1) ? row[k] : -1e30f;
    }

    float m = -1e30f;
    #pragma unroll
    for (int p = 0; p < 4; p++) m = fmaxf(m, rv[p]);
    #pragma unroll
    for (int off = 16; off; off >>= 1) m = fmaxf(m, __shfl_xor_sync(0xffffffffu, m, off));
    if (lane == 0) sh[warp] = m;
    __syncthreads();
    if (warp == 0) {
        float t = (lane < 8) ? sh[lane] : -1e30f;
        #pragma unroll
        for (int off = 16; off; off >>= 1) t = fmaxf(t, __shfl_xor_sync(0xffffffffu, t, off));
        if (lane == 0) sh[0] = t;
    }
    __syncthreads();
    m = sh[0];
    __syncthreads();

    float s = 0.f;
    float ev[4];
    #pragma unroll
    for (int p = 0; p < 4; p++) {
        int k = tid + 256 * p;
        float e = (k < NM1) ? __expf(rv[p] - m) : 0.f;
        ev[p] = e;
        s += e;
    }
    #pragma unroll
    for (int off = 16; off; off >>= 1) s += __shfl_xor_sync(0xffffffffu, s, off);
    if (lane == 0) sh[warp] = s;
    __syncthreads();
    if (warp == 0) {
        float t = (lane < 8) ? sh[lane] : 0.f;
        #pragma unroll
        for (int off = 16; off; off >>= 1) t += __shfl_xor_sync(0xffffffffu, t, off);
        if (lane == 0) sh[0] = t;
    }
    __syncthreads();
    const float inv = 1.f / sh[0];

    #pragma unroll
    for (int p = 0; p < 4; p++) {
        int k = tid + 256 * p;
        if (k < NM1) {
            int j = (k < i) ? k : k + 1;
            o[j] = f2tf32f(ev[p] * inv);
        }
    }
    if (tid == 0) o[i] = 0.f;
}

// ---------------------------------------------------------------------------
// Heads epilogue: out[r][c] from ho (32000 x 75), biases, anchors.
// ---------------------------------------------------------------------------
__global__ __launch_bounds__(256)
void heads_epilogue_kernel(const float* __restrict__ ho,
                           const float* __restrict__ cls_b,
                           const float* __restrict__ reg_b,
                           const float* __restrict__ anchors,
                           float* __restrict__ out)
{
    int idx = blockIdx.x * blockDim.x + threadIdx.x;
    if (idx >= BB * NN * OUTC) return;
    int c = idx % OUTC;
    int r = idx / OUTC;
    int n = r % NN;
    float v;
    if (c < 2)       v = ho[(size_t)r * HN + c] + cls_b[c];
    else if (c < 4)  v = anchors[n * OUTC + c];
    else             v = ho[(size_t)r * HN + (c - 2)] + reg_b[c - 4]
                         + anchors[n * OUTC + c];
    out[idx] = v;
}

// ---------------------------------------------------------------------------
// Launch
// ---------------------------------------------------------------------------
extern "C" void kernel_launch(void* const* d_in, const int* in_sizes, int n_in,
                              void* d_out, int out_size)
{
    const float* fv      = (const float*)d_in[0];
    const float* attn_w  = (const float*)d_in[1];
    const float* attn_b  = (const float*)d_in[2];
    const float* cls_w   = (const float*)d_in[3];
    const float* cls_b   = (const float*)d_in[4];
    const float* reg_w   = (const float*)d_in[5];
    const float* reg_b   = (const float*)d_in[6];
    const float* anchors = (const float*)d_in[7];
    const int*   z       = (const int*)d_in[8];
    const int*   y       = (const int*)d_in[9];
    const int*   x       = (const int*)d_in[10];
    const void*  mask    = d_in[11];
    float* out = (float*)d_out;

    float *feat, *logits, *S, *att, *ho, *W, *Bt;
    cudaGetSymbolAddress((void**)&feat,   g_feat);
    cudaGetSymbolAddress((void**)&logits, g_logits);
    cudaGetSymbolAddress((void**)&S,      g_S);
    cudaGetSymbolAddress((void**)&att,    g_att);
    cudaGetSymbolAddress((void**)&ho,     g_ho);
    cudaGetSymbolAddress((void**)&W,      g_W);
    cudaGetSymbolAddress((void**)&Bt,     g_Bt);

    static int attr_done = 0;
    if (!attr_done) {
        cudaFuncSetAttribute(gemm_tf32_cp_kernel<0, true,  true,  false>,
                             cudaFuncAttributeMaxDynamicSharedMemorySize, GEMM_SMEM);
        cudaFuncSetAttribute(gemm_tf32_cp_kernel<0, false, true,  true>,
                             cudaFuncAttributeMaxDynamicSharedMemorySize, GEMM_SMEM);
        cudaFuncSetAttribute(gemm_tf32_cp_kernel<1, false, false, false>,
                             cudaFuncAttributeMaxDynamicSharedMemorySize, GEMM_SMEM);
        attr_done = 1;
    }

    // 1) mask dtype detection
    detect_mask_kernel<<<1, 256>>>((const unsigned int*)mask, 190000);

    // 2) gather (tf32-rounded output)
    {
        int total = BB * NN * DD;
        gather_kernel<<<(total + 255) / 256, 256>>>(fv, z, y, x, mask, feat, total);
    }

    // 2b) prep attn_w (pad+round) and pack heads weights (round)
    prep_attnw_kernel<<<(DD * BTPAD + 255) / 256, 256>>>(attn_w, Bt);
    pack_w_kernel<<<(2 * DD * HN + 255) / 256, 256>>>(cls_w, reg_w, W);

    // 3) logits = feat @ attn_w + attn_b   (per batch 1000x999, K=768; padded B, vec)
    {
        dim3 grid((NM1 + 127) / 128, (NN + 127) / 128, BB);
        gemm_tf32_cp_kernel<0, true, true, false><<<grid, 256, GEMM_SMEM>>>(
            feat, nullptr, Bt, attn_b, logits,
            NN, NM1, DD, DD, BTPAD,
            (size_t)NN * DD, 0, (size_t)NN * NM1);
    }

    // 4) softmax + scatter (tf32-rounded output)
    {
        dim3 grid(NN, BB);
        softmax_scatter_kernel<<<grid, 256>>>(logits, S);
    }

    // 5) att = S @ feat   (per batch 1000x768, K=1000; vec B; tf32-rounded output)
    {
        dim3 grid((DD + 127) / 128, (NN + 127) / 128, BB);
        gemm_tf32_cp_kernel<0, false, true, true><<<grid, 256, GEMM_SMEM>>>(
            S, nullptr, feat, nullptr, att,
            NN, DD, NN, NN, DD,
            (size_t)NN * NN, (size_t)NN * DD, (size_t)NN * DD);
    }

    // 6) heads GEMM: [att|feat] (32000 x 1536) @ W (1536 x 75; scalar B)
    {
        dim3 grid(1, (BB * NN + 127) / 128, 1);
        gemm_tf32_cp_kernel<1, false, false, false><<<grid, 256, GEMM_SMEM>>>(
            att, feat, W, nullptr, ho,
            BB * NN, HN, 2 * DD, 0, HN,
            0, 0, 0);
    }

    // 7) heads epilogue
    {
        int total = BB * NN * OUTC;
        heads_epilogue_kernel<<<(total + 255) / 256, 256>>>(ho, cls_b, reg_b,
                                                            anchors, out);
    }
}

// round 12
// speedup vs baseline: 2.6551x; 1.0529x over previous
#include <cuda_runtime.h>
#include <cuda_bf16.h>
#include <math.h>

// Problem constants
#define BB 32
#define NN 1000
#define CC 64
#define HF 12
#define WF 20
#define DD 768          // C*HF
#define NM1 999         // N-1
#define YD 72
#define OUTC 77         // 2 + 2 + 73
#define HN 75           // heads output cols (2 cls + 73 reg)
#define BTPAD 1000      // padded attn_w row stride

// GEMM smem layout (floats)
#define SA_STRIDE 36            // 32 k + 4 pad
#define SB_STRIDE 136           // 128 n + 8 pad
#define SA_STAGE  (128 * SA_STRIDE)   // 4608
#define SB_STAGE  (32 * SB_STRIDE)    // 4352
#define SB_BASE   (2 * SA_STAGE)      // 9216
#define GEMM_SMEM ((2 * SA_STAGE + 2 * SB_STAGE) * 4)   // 71680 bytes

// ---------------------------------------------------------------------------
// Scratch (device globals; no runtime allocation allowed)
// ---------------------------------------------------------------------------
__device__ float g_feat[BB * NN * DD];        // (B,N,768) tf32-rounded
__device__ float g_logits[BB * NN * NM1];     // (B,N,999) fp32
__device__ float g_S[BB * NN * NN];           // (B,N,N) tf32-rounded softmax
__device__ float g_att[BB * NN * DD];         // (B,N,768) tf32-rounded
__device__ float g_ho[BB * NN * HN];          // heads GEMM result (32000 x 75)
__device__ float g_W[2 * DD * HN];            // packed [cls_w|reg_w], tf32-rounded
__device__ float g_Bt[DD * BTPAD];            // attn_w padded + rounded
__device__ int   g_mask_mode;                 // 1 = byte mask, 0 = 4-byte mask

// ---------------------------------------------------------------------------
// PTX helpers
// ---------------------------------------------------------------------------
__device__ __forceinline__ unsigned int smem_u32(const void* p)
{
    unsigned int a;
    asm("{ .reg .u64 t; cvta.to.shared.u64 t, %1; cvt.u32.u64 %0, t; }"
        : "=r"(a) : "l"(p));
    return a;
}

__device__ __forceinline__ void cp_async16(unsigned int dst, const void* src, int sz)
{
    asm volatile("cp.async.ca.shared.global [%0], [%1], 16, %2;"
                 :: "r"(dst), "l"(src), "r"(sz));
}

__device__ __forceinline__ void cp_async4(unsigned int dst, const void* src, int sz)
{
    asm volatile("cp.async.ca.shared.global [%0], [%1], 4, %2;"
                 :: "r"(dst), "l"(src), "r"(sz));
}

__device__ __forceinline__ void cp_commit()
{
    asm volatile("cp.async.commit_group;");
}

template<int N>
__device__ __forceinline__ void cp_wait()
{
    asm volatile("cp.async.wait_group %0;" :: "n"(N));
}

__device__ __forceinline__ float f2tf32f(float f)
{
    unsigned int r;
    asm("cvt.rna.tf32.f32 %0, %1;" : "=r"(r) : "f"(f));
    return __uint_as_float(r);
}

// ---------------------------------------------------------------------------
// Mask dtype detection (bool/uint8 vs int32/float32)
// ---------------------------------------------------------------------------
__global__ __launch_bounds__(256)
void detect_mask_kernel(const unsigned int* __restrict__ w, int nwords)
{
    __shared__ int bad;
    if (threadIdx.x == 0) bad = 0;
    __syncthreads();
    int local = 0;
    for (int k = threadIdx.x; k < nwords; k += blockDim.x) {
        unsigned int v = w[k];
        if (v != 0u && v != 1u && v != 0x3F800000u) local = 1;
    }
    if (local) bad = 1;
    __syncthreads();
    if (threadIdx.x == 0) g_mask_mode = bad;   // 1 => byte mask
}

// ---------------------------------------------------------------------------
// Gather (writes tf32-rounded feat)
// ---------------------------------------------------------------------------
__global__ __launch_bounds__(256)
void gather_kernel(const float* __restrict__ fv,
                   const int* __restrict__ z,
                   const int* __restrict__ y,
                   const int* __restrict__ x,
                   const void* __restrict__ mask,
                   float* __restrict__ feat,
                   int total)
{
    int idx = blockIdx.x * blockDim.x + threadIdx.x;
    if (idx >= total) return;
    int d = idx % DD;
    int rest = idx / DD;
    int n = rest % NN;
    int b = rest / NN;
    int nd = n * DD + d;

    bool inv;
    if (g_mask_mode)
        inv = ((const unsigned char*)mask)[nd] != 0;
    else
        inv = ((const unsigned int*)mask)[nd] != 0u;

    float v = 0.f;
    if (!inv) {
        int zz = z[nd], yy = y[nd], xx = x[nd];
        v = fv[((b * CC + zz) * HF + yy) * WF + xx];
    }
    feat[idx] = f2tf32f(v);
}

// ---------------------------------------------------------------------------
// Prep attn_w: pad 999 -> 1000 row stride + tf32 round.
// ---------------------------------------------------------------------------
__global__ __launch_bounds__(256)
void prep_attnw_kernel(const float* __restrict__ w, float* __restrict__ out)
{
    int idx = blockIdx.x * blockDim.x + threadIdx.x;
    if (idx >= DD * BTPAD) return;
    int k = idx / BTPAD, n = idx % BTPAD;
    out[idx] = (n < NM1) ? f2tf32f(w[k * NM1 + n]) : 0.f;
}

// ---------------------------------------------------------------------------
// Pack heads weights (tf32-rounded)
// ---------------------------------------------------------------------------
__global__ __launch_bounds__(256)
void pack_w_kernel(const float* __restrict__ cls_w,
                   const float* __restrict__ reg_w,
                   float* __restrict__ W)
{
    int idx = blockIdx.x * blockDim.x + threadIdx.x;
    if (idx >= 2 * DD * HN) return;
    int k = idx / HN, c = idx % HN;
    float v = (c < 2) ? cls_w[k * 2 + c] : reg_w[k * 73 + (c - 2)];
    W[idx] = f2tf32f(v);
}

// ---------------------------------------------------------------------------
// TF32 tensor-core GEMM, 128x128 block, Ktile 32, 128 threads, 4 warps,
// warp tile 64x64 (4 m16 x 8 n8).  Operands pre-rounded to tf32.
//   As[m][k] stride 36  (conflict-free fragment loads)
//   Bs[k][n] stride 136 (conflict-free fragment loads)
// 2-stage cp.async pipeline, ONE __syncthreads per K-tile.
// MODE 0: plain A (stride lda). MODE 1: concat A=[A1|A2] rows of DD each.
// VECB: 16B B copies (ldb%4==0). ROUND_OUT: tf32-round C before store.
// ---------------------------------------------------------------------------
template<int MODE, bool ADD_BIAS, bool VECB, bool ROUND_OUT>
__global__ __launch_bounds__(128, 2)
void gemm_tf32_cp_kernel(const float* __restrict__ A,
                         const float* __restrict__ A2,
                         const float* __restrict__ B,
                         const float* __restrict__ bias,
                         float* __restrict__ C,
                         int M, int N, int K, int lda, int ldb,
                         size_t sA, size_t sB, size_t sC)
{
    extern __shared__ float sm[];

    const int tid  = threadIdx.x;
    const int lane = tid & 31;
    const int wid  = tid >> 5;          // 0..3
    const int gid  = lane >> 2;         // 0..7
    const int tg   = lane & 3;          // 0..3
    const int wm   = (wid & 1) * 64;
    const int wn   = (wid >> 1) * 64;

    const int m0 = blockIdx.y * 128;
    const int n0 = blockIdx.x * 128;

    if (MODE == 0) A += (size_t)blockIdx.z * sA;
    B += (size_t)blockIdx.z * sB;
    C += (size_t)blockIdx.z * sC;

    const unsigned int smA_u = smem_u32(sm);
    const unsigned int smB_u = smem_u32(sm + SB_BASE);

    float acc[4][8][4];
    #pragma unroll
    for (int i = 0; i < 4; i++)
        #pragma unroll
        for (int j = 0; j < 8; j++)
            #pragma unroll
            for (int q = 0; q < 4; q++) acc[i][j][q] = 0.f;

    // ---- stage: cp.async A-tile and B-tile for kt into stage st
    auto stage = [&](int kt, int st) {
        unsigned int abase = smA_u + st * (SA_STAGE * 4);
        #pragma unroll
        for (int i = 0; i < 8; i++) {
            int c   = tid + i * 128;
            int m_l = c >> 3, kq = c & 7;
            int m = m0 + m_l, kg = kt + kq * 4;
            const float* src;
            int sz = 0;
            if (m < M && kg < K) {
                if (MODE == 1)
                    src = (kg < DD) ? &A[(size_t)m * DD + kg]
                                    : &A2[(size_t)m * DD + (kg - DD)];
                else
                    src = &A[(size_t)m * lda + kg];
                int rem = (K - kg) * 4;
                sz = rem < 16 ? rem : 16;
            } else {
                src = A;
            }
            cp_async16(abase + (m_l * SA_STRIDE + kq * 4) * 4, src, sz);
        }
        unsigned int bbase = smB_u + st * (SB_STAGE * 4);
        if (VECB) {
            #pragma unroll
            for (int i = 0; i < 8; i++) {
                int c   = tid + i * 128;
                int k_l = c >> 5, nq = c & 31;
                int kg = kt + k_l;
                const float* src = (kg < K) ? &B[(size_t)kg * ldb + n0 + nq * 4] : B;
                int sz = (kg < K) ? 16 : 0;
                cp_async16(bbase + (k_l * SB_STRIDE + nq * 4) * 4, src, sz);
            }
        } else {
            #pragma unroll
            for (int i = 0; i < 32; i++) {
                int c   = tid + i * 128;
                int k_l = c >> 7, n_l = c & 127;
                int kg = kt + k_l, n = n0 + n_l;
                bool ok = (kg < K) && (n < N);
                const float* src = ok ? &B[(size_t)kg * ldb + n] : B;
                cp_async4(bbase + (k_l * SB_STRIDE + n_l) * 4, src, ok ? 4 : 0);
            }
        }
    };

    auto compute = [&](int st) {
        const unsigned int* Ab = (const unsigned int*)(sm + st * SA_STAGE);
        const unsigned int* Bb = (const unsigned int*)(sm + SB_BASE + st * SB_STAGE);
        #pragma unroll
        for (int ks = 0; ks < 4; ks++) {
            const int k0 = ks * 8;
            unsigned int a[4][4], bf[8][2];
            #pragma unroll
            for (int mt = 0; mt < 4; mt++) {
                int ar = wm + mt * 16 + gid;
                a[mt][0] = Ab[ar       * SA_STRIDE + k0 + tg];
                a[mt][1] = Ab[(ar + 8) * SA_STRIDE + k0 + tg];
                a[mt][2] = Ab[ar       * SA_STRIDE + k0 + tg + 4];
                a[mt][3] = Ab[(ar + 8) * SA_STRIDE + k0 + tg + 4];
            }
            #pragma unroll
            for (int nt = 0; nt < 8; nt++) {
                int bc = wn + nt * 8 + gid;
                bf[nt][0] = Bb[(k0 + tg)     * SB_STRIDE + bc];
                bf[nt][1] = Bb[(k0 + tg + 4) * SB_STRIDE + bc];
            }
            #pragma unroll
            for (int mt = 0; mt < 4; mt++)
                #pragma unroll
                for (int nt = 0; nt < 8; nt++) {
                    asm volatile(
                        "mma.sync.aligned.m16n8k8.row.col.f32.tf32.tf32.f32 "
                        "{%0,%1,%2,%3}, {%4,%5,%6,%7}, {%8,%9}, {%0,%1,%2,%3};\n"
                        : "+f"(acc[mt][nt][0]), "+f"(acc[mt][nt][1]),
                          "+f"(acc[mt][nt][2]), "+f"(acc[mt][nt][3])
                        : "r"(a[mt][0]), "r"(a[mt][1]), "r"(a[mt][2]), "r"(a[mt][3]),
                          "r"(bf[nt][0]), "r"(bf[nt][1]));
                }
        }
    };

    // ---- 2-stage pipeline, one sync per tile ----
    // Invariant at top of iter t (after sync): all warps finished reading
    // buffer (t+1)&1 (it was computed at iter t-1), so staging into it is safe.
    stage(0, 0);
    cp_commit();

    int st = 0;
    for (int kt = 0; kt < K; kt += 32) {
        cp_wait<0>();
        __syncthreads();
        if (kt + 32 < K) {
            stage(kt + 32, st ^ 1);
            cp_commit();
        }
        compute(st);
        st ^= 1;
    }

    // ---- epilogue ----
    #pragma unroll
    for (int mt = 0; mt < 4; mt++) {
        #pragma unroll
        for (int nt = 0; nt < 8; nt++) {
            int row0 = m0 + wm + mt * 16 + gid;
            int col0 = n0 + wn + nt * 8 + tg * 2;
            #pragma unroll
            for (int q = 0; q < 4; q++) {
                int row = row0 + (q >> 1) * 8;
                int col = col0 + (q & 1);
                if (row < M && col < N) {
                    float v = acc[mt][nt][q];
                    if (ADD_BIAS) v += bias[col];
                    if (ROUND_OUT) v = f2tf32f(v);
                    C[(size_t)row * N + col] = v;
                }
            }
        }
    }
}

// ---------------------------------------------------------------------------
// Row softmax over 999 logits + scatter into (N x N) with zero diagonal.
// Output tf32-rounded (consumed only by GEMM2 A).
// ---------------------------------------------------------------------------
__global__ __launch_bounds__(256)
void softmax_scatter_kernel(const float* __restrict__ logits,
                            float* __restrict__ S)
{
    const int i = blockIdx.x;
    const int b = blockIdx.y;
    const float* __restrict__ row = logits + ((size_t)(b * NN + i)) * NM1;
    float* __restrict__ o = S + ((size_t)(b * NN + i)) * NN;

    __shared__ float sh[8];
    const int tid = threadIdx.x;
    const int lane = tid & 31, warp = tid >> 5;

    float rv[4];
    #pragma unroll
    for (int p = 0; p < 4; p++) {
        int k = tid + 256 * p;
        rv[p] = (k < NM1) ? row[k] : -1e30f;
    }

    float m = -1e30f;
    #pragma unroll
    for (int p = 0; p < 4; p++) m = fmaxf(m, rv[p]);
    #pragma unroll
    for (int off = 16; off; off >>= 1) m = fmaxf(m, __shfl_xor_sync(0xffffffffu, m, off));
    if (lane == 0) sh[warp] = m;
    __syncthreads();
    if (warp == 0) {
        float t = (lane < 8) ? sh[lane] : -1e30f;
        #pragma unroll
        for (int off = 16; off; off >>= 1) t = fmaxf(t, __shfl_xor_sync(0xffffffffu, t, off));
        if (lane == 0) sh[0] = t;
    }
    __syncthreads();
    m = sh[0];
    __syncthreads();

    float s = 0.f;
    float ev[4];
    #pragma unroll
    for (int p = 0; p < 4; p++) {
        int k = tid + 256 * p;
        float e = (k < NM1) ? __expf(rv[p] - m) : 0.f;
        ev[p] = e;
        s += e;
    }
    #pragma unroll
    for (int off = 16; off; off >>= 1) s += __shfl_xor_sync(0xffffffffu, s, off);
    if (lane == 0) sh[warp] = s;
    __syncthreads();
    if (warp == 0) {
        float t = (lane < 8) ? sh[lane] : 0.f;
        #pragma unroll
        for (int off = 16; off; off >>= 1) t += __shfl_xor_sync(0xffffffffu, t, off);
        if (lane == 0) sh[0] = t;
    }
    __syncthreads();
    const float inv = 1.f / sh[0];

    #pragma unroll
    for (int p = 0; p < 4; p++) {
        int k = tid + 256 * p;
        if (k < NM1) {
            int j = (k < i) ? k : k + 1;
            o[j] = f2tf32f(ev[p] * inv);
        }
    }
    if (tid == 0) o[i] = 0.f;
}

// ---------------------------------------------------------------------------
// Heads epilogue: out[r][c] from ho (32000 x 75), biases, anchors.
// ---------------------------------------------------------------------------
__global__ __launch_bounds__(256)
void heads_epilogue_kernel(const float* __restrict__ ho,
                           const float* __restrict__ cls_b,
                           const float* __restrict__ reg_b,
                           const float* __restrict__ anchors,
                           float* __restrict__ out)
{
    int idx = blockIdx.x * blockDim.x + threadIdx.x;
    if (idx >= BB * NN * OUTC) return;
    int c = idx % OUTC;
    int r = idx / OUTC;
    int n = r % NN;
    float v;
    if (c < 2)       v = ho[(size_t)r * HN + c] + cls_b[c];
    else if (c < 4)  v = anchors[n * OUTC + c];
    else             v = ho[(size_t)r * HN + (c - 2)] + reg_b[c - 4]
                         + anchors[n * OUTC + c];
    out[idx] = v;
}

// ---------------------------------------------------------------------------
// Launch
// ---------------------------------------------------------------------------
extern "C" void kernel_launch(void* const* d_in, const int* in_sizes, int n_in,
                              void* d_out, int out_size)
{
    const float* fv      = (const float*)d_in[0];
    const float* attn_w  = (const float*)d_in[1];
    const float* attn_b  = (const float*)d_in[2];
    const float* cls_w   = (const float*)d_in[3];
    const float* cls_b   = (const float*)d_in[4];
    const float* reg_w   = (const float*)d_in[5];
    const float* reg_b   = (const float*)d_in[6];
    const float* anchors = (const float*)d_in[7];
    const int*   z       = (const int*)d_in[8];
    const int*   y       = (const int*)d_in[9];
    const int*   x       = (const int*)d_in[10];
    const void*  mask    = d_in[11];
    float* out = (float*)d_out;

    float *feat, *logits, *S, *att, *ho, *W, *Bt;
    cudaGetSymbolAddress((void**)&feat,   g_feat);
    cudaGetSymbolAddress((void**)&logits, g_logits);
    cudaGetSymbolAddress((void**)&S,      g_S);
    cudaGetSymbolAddress((void**)&att,    g_att);
    cudaGetSymbolAddress((void**)&ho,     g_ho);
    cudaGetSymbolAddress((void**)&W,      g_W);
    cudaGetSymbolAddress((void**)&Bt,     g_Bt);

    static int attr_done = 0;
    if (!attr_done) {
        cudaFuncSetAttribute(gemm_tf32_cp_kernel<0, true,  true,  false>,
                             cudaFuncAttributeMaxDynamicSharedMemorySize, GEMM_SMEM);
        cudaFuncSetAttribute(gemm_tf32_cp_kernel<0, false, true,  true>,
                             cudaFuncAttributeMaxDynamicSharedMemorySize, GEMM_SMEM);
        cudaFuncSetAttribute(gemm_tf32_cp_kernel<1, false, false, false>,
                             cudaFuncAttributeMaxDynamicSharedMemorySize, GEMM_SMEM);
        attr_done = 1;
    }

    // 1) mask dtype detection
    detect_mask_kernel<<<1, 256>>>((const unsigned int*)mask, 190000);

    // 2) gather (tf32-rounded output)
    {
        int total = BB * NN * DD;
        gather_kernel<<<(total + 255) / 256, 256>>>(fv, z, y, x, mask, feat, total);
    }

    // 2b) prep attn_w (pad+round) and pack heads weights (round)
    prep_attnw_kernel<<<(DD * BTPAD + 255) / 256, 256>>>(attn_w, Bt);
    pack_w_kernel<<<(2 * DD * HN + 255) / 256, 256>>>(cls_w, reg_w, W);

    // 3) logits = feat @ attn_w + attn_b   (per batch 1000x999, K=768; padded B, vec)
    {
        dim3 grid((NM1 + 127) / 128, (NN + 127) / 128, BB);
        gemm_tf32_cp_kernel<0, true, true, false><<<grid, 128, GEMM_SMEM>>>(
            feat, nullptr, Bt, attn_b, logits,
            NN, NM1, DD, DD, BTPAD,
            (size_t)NN * DD, 0, (size_t)NN * NM1);
    }

    // 4) softmax + scatter (tf32-rounded output)
    {
        dim3 grid(NN, BB);
        softmax_scatter_kernel<<<grid, 256>>>(logits, S);
    }

    // 5) att = S @ feat   (per batch 1000x768, K=1000; vec B; tf32-rounded output)
    {
        dim3 grid((DD + 127) / 128, (NN + 127) / 128, BB);
        gemm_tf32_cp_kernel<0, false, true, true><<<grid, 128, GEMM_SMEM>>>(
            S, nullptr, feat, nullptr, att,
            NN, DD, NN, NN, DD,
            (size_t)NN * NN, (size_t)NN * DD, (size_t)NN * DD);
    }

    // 6) heads GEMM: [att|feat] (32000 x 1536) @ W (1536 x 75; scalar B)
    {
        dim3 grid(1, (BB * NN + 127) / 128, 1);
        gemm_tf32_cp_kernel<1, false, false, false><<<grid, 128, GEMM_SMEM>>>(
            att, feat, W, nullptr, ho,
            BB * NN, HN, 2 * DD, 0, HN,
            0, 0, 0);
    }

    // 7) heads epilogue
    {
        int total = BB * NN * OUTC;
        heads_epilogue_kernel<<<(total + 255) / 256, 256>>>(ho, cls_b, reg_b,
                                                            anchors, out);
    }
}